// round 17
// baseline (speedup 1.0000x reference)
#include <cuda_runtime.h>
#include <cuda_bf16.h>
#include <cstdint>

// Swin window attention. R17 = R16 base + cp.async double-buffered W staging
// in qkv/proj (replaces scalar __ldg W fragments; LDS+cvt instead of L2-latency
// LDG in the MMA dependence chain). Attention identical to R16.
// B=64, H=W=56, C=128, heads=4, hd=32, ws=7, L=49.

#define TOKENS   200704
#define WH_TOTAL 16384
#define QKV_ELEMS (3ull * 16384ull * 49ull * 32ull)
#define ATT_ELEMS ((size_t)TOKENS * 128)
#define COMB_ELEMS (64 * 4 * 2401)   // [win][head][ij]

__device__ float g_qkv[QKV_ELEMS];   // tf32 bits: [(s*16384 + wh)*49 + l]*32 + d
__device__ float g_att[ATT_ELEMS];   // tf32 bits: [b,h,w,c] pre-projection
__device__ float g_comb[COMB_ELEMS]; // relt[relidx[ij]][head] + mask[win][ij]

// ---------------------------------------------------------------------------
__device__ __forceinline__ uint32_t f2tf32(float x) {
    uint32_t r;
    asm("cvt.rna.tf32.f32 %0, %1;" : "=r"(r) : "f"(x));
    return r;
}
__device__ __forceinline__ void mma_tf32(float (&d)[4], const uint32_t* a, const uint32_t* b) {
    asm volatile("mma.sync.aligned.m16n8k8.row.col.f32.tf32.tf32.f32 "
                 "{%0,%1,%2,%3}, {%4,%5,%6,%7}, {%8,%9}, {%0,%1,%2,%3};"
                 : "+f"(d[0]), "+f"(d[1]), "+f"(d[2]), "+f"(d[3])
                 : "r"(a[0]), "r"(a[1]), "r"(a[2]), "r"(a[3]), "r"(b[0]), "r"(b[1]));
}
__device__ __forceinline__ void ldsm_x4(uint32_t (&r)[4], const uint32_t* p) {
    uint32_t a = (uint32_t)__cvta_generic_to_shared(p);
    asm volatile("ldmatrix.sync.aligned.m8n8.x4.shared.b16 {%0,%1,%2,%3}, [%4];"
                 : "=r"(r[0]), "=r"(r[1]), "=r"(r[2]), "=r"(r[3]) : "r"(a));
}
__device__ __forceinline__ int ldsm_off(int lane, int row0, int stride) {
    return (row0 + (lane & 15)) * stride + ((lane >> 4) << 2);
}
__device__ __forceinline__ void cp_async16(uint32_t dst, const void* src) {
    asm volatile("cp.async.ca.shared.global [%0], [%1], 16;" :: "r"(dst), "l"(src));
}
#define CP_COMMIT() asm volatile("cp.async.commit_group;" ::: "memory")
template<int N> __device__ __forceinline__ void cp_wait() {
    asm volatile("cp.async.wait_group %0;" :: "n"(N) : "memory");
}

#define A_STR 132
#define A_WORDS (128 * A_STR)          // 16896
#define W_STR 132
#define WBUF_WORDS (16 * W_STR)        // 2112 per buffer
#define SM_GEMM_WORDS (A_WORDS + 2 * WBUF_WORDS)   // 21120
#define SM_GEMM_BYTES (SM_GEMM_WORDS * 4)          // 84480

// ---------------------------------------------------------------------------
// Kernel 0: combine relative-position bias and window mask.
// ---------------------------------------------------------------------------
__global__ __launch_bounds__(256) void combine_bias(
    const int* __restrict__ relidx, const float* __restrict__ mask,
    const float* __restrict__ relt)
{
    int i = blockIdx.x * 256 + threadIdx.x;
    if (i < COMB_ELEMS) {
        int ij = i % 2401;
        int wh = i / 2401;
        int head = wh & 3, win = wh >> 2;
        g_comb[i] = __ldg(relt + __ldg(relidx + ij) * 4 + head)
                  + __ldg(mask + (size_t)win * 2401 + ij);
    }
}

// ---------------------------------------------------------------------------
// Kernel 1: QKV GEMM. grid=1568, 256 threads (8 warps: 2m x 4n). A in smem,
// W staged via cp.async double buffer (16-k chunks, pipelined across s).
// ---------------------------------------------------------------------------
__global__ __launch_bounds__(256, 2) void qkv_gemm_mma(
    const float* __restrict__ A, const float* __restrict__ W,
    const float* __restrict__ bias)
{
    extern __shared__ uint32_t As[];
    float* Wsf = (float*)(As + A_WORDS);
    uint32_t ws_u32 = (uint32_t)__cvta_generic_to_shared(Wsf);

    int tid = threadIdx.x, bm = blockIdx.x;
    int lane = tid & 31, warp = tid >> 5;
    int g = lane >> 2, t = lane & 3;
    int m0 = (warp >> 2) * 64, n0 = (warp & 3) * 32;
    int head = warp & 3;
    int wrow = tid >> 4, wcol = (tid & 15) * 8;   // chunk copy mapping

    // issue chunk 0 (s=0, k=0..15) first so it flies during the A load
    {
        const float* src = W + (size_t)wrow * 384 + wcol;
        uint32_t dst = ws_u32 + (uint32_t)(wrow * W_STR + wcol) * 4;
        cp_async16(dst, src);
        cp_async16(dst + 16, src + 4);
        CP_COMMIT();
    }

    {
        const float4* Ap = (const float4*)(A + (size_t)bm * 128 * 128);
        for (int i = tid; i < 4096; i += 256) {
            int r = i >> 5, c = (i & 31) << 2;
            float4 v = Ap[i];
            uint4 u = make_uint4(f2tf32(v.x), f2tf32(v.y), f2tf32(v.z), f2tf32(v.w));
            *(uint4*)&As[r * A_STR + c] = u;
        }
    }

    int whbase[8], lwin8[8];
#pragma unroll
    for (int mt = 0; mt < 4; mt++)
#pragma unroll
        for (int h = 0; h < 2; h++) {
            int m = bm * 128 + m0 + mt * 16 + g + h * 8;
            int bimg = m / 3136;
            int rem  = m - bimg * 3136;
            int y = rem / 56, xx = rem - y * 56;
            int nhi = y / 7,  wy = y - nhi * 7;
            int nwi = xx / 7, wx = xx - nwi * 7;
            whbase[mt * 2 + h] = (bimg * 64 + nhi * 8 + nwi) * 4 + head;
            lwin8[mt * 2 + h]  = wy * 7 + wx;
        }
    int aoff[4];
#pragma unroll
    for (int mt = 0; mt < 4; mt++)
        aoff[mt] = ldsm_off(lane, m0 + mt * 16, A_STR);
    __syncthreads();

#pragma unroll 1
    for (int s = 0; s < 3; s++) {
        float acc[4][4][4] = {};
#pragma unroll 1
        for (int c = 0; c < 8; c++) {
            int cc = s * 8 + c;
            if (cc < 23) {
                int nc = cc + 1;
                const float* src = W + (size_t)((nc & 7) * 16 + wrow) * 384
                                 + (nc >> 3) * 128 + wcol;
                uint32_t dst = ws_u32
                             + (uint32_t)(((nc & 1) * 16 + wrow) * W_STR + wcol) * 4;
                cp_async16(dst, src);
                cp_async16(dst + 16, src + 4);
            }
            CP_COMMIT();
            if (cc < 23) cp_wait<1>(); else cp_wait<0>();
            __syncthreads();

            const float* wb = Wsf + (cc & 1) * WBUF_WORDS;
#pragma unroll
            for (int kk = 0; kk < 2; kk++) {
                uint32_t b[4][2];
                const float* w0 = wb + (kk * 8 + t) * W_STR + n0 + g;
                const float* w1 = w0 + 4 * W_STR;
#pragma unroll
                for (int nt = 0; nt < 4; nt++) {
                    b[nt][0] = f2tf32(w0[nt * 8]);
                    b[nt][1] = f2tf32(w1[nt * 8]);
                }
                uint32_t a[4][4];
                int k0 = c * 16 + kk * 8;
#pragma unroll
                for (int mt = 0; mt < 4; mt++)
                    ldsm_x4(a[mt], As + aoff[mt] + k0);
#pragma unroll
                for (int mt = 0; mt < 4; mt++)
#pragma unroll
                    for (int nt = 0; nt < 4; nt++)
                        mma_tf32(acc[mt][nt], a[mt], b[nt]);
            }
            __syncthreads();   // buffer reuse safety (refilled at cc+2)
        }

        float bb[4][2];
#pragma unroll
        for (int nt = 0; nt < 4; nt++) {
            int d = nt * 8 + 2 * t;
            bb[nt][0] = bias[s * 128 + head * 32 + d];
            bb[nt][1] = bias[s * 128 + head * 32 + d + 1];
        }
#pragma unroll
        for (int mt = 0; mt < 4; mt++)
#pragma unroll
            for (int h = 0; h < 2; h++) {
                int idx = mt * 2 + h;
                size_t dst0 = ((size_t)(s * 16384 + whbase[idx]) * 49 + lwin8[idx]) * 32;
#pragma unroll
                for (int nt = 0; nt < 4; nt++) {
                    int d = nt * 8 + 2 * t;
                    uint2 v = make_uint2(f2tf32(acc[mt][nt][2 * h]     + bb[nt][0]),
                                         f2tf32(acc[mt][nt][2 * h + 1] + bb[nt][1]));
                    *(uint2*)&g_qkv[dst0 + d] = v;
                }
            }
    }
}

// ---------------------------------------------------------------------------
// Kernel 3: projection GEMM. Same cp.async W staging (8 chunks, N=128).
// ---------------------------------------------------------------------------
__global__ __launch_bounds__(256, 2) void proj_gemm_mma(
    const float* __restrict__ W, const float* __restrict__ bias,
    float* __restrict__ out)
{
    extern __shared__ uint32_t As[];
    float* Wsf = (float*)(As + A_WORDS);
    uint32_t ws_u32 = (uint32_t)__cvta_generic_to_shared(Wsf);

    int tid = threadIdx.x, bm = blockIdx.x;
    int lane = tid & 31, warp = tid >> 5;
    int g = lane >> 2, t = lane & 3;
    int m0 = (warp >> 2) * 64, n0 = (warp & 3) * 32;
    int wrow = tid >> 4, wcol = (tid & 15) * 8;

    {
        const float* src = W + (size_t)wrow * 128 + wcol;
        uint32_t dst = ws_u32 + (uint32_t)(wrow * W_STR + wcol) * 4;
        cp_async16(dst, src);
        cp_async16(dst + 16, src + 4);
        CP_COMMIT();
    }

    {
        const uint4* Ap = (const uint4*)(g_att + (size_t)bm * 128 * 128);
        for (int i = tid; i < 4096; i += 256) {
            int r = i >> 5, c = (i & 31) << 2;
            *(uint4*)&As[r * A_STR + c] = Ap[i];
        }
    }
    int aoff[4];
#pragma unroll
    for (int mt = 0; mt < 4; mt++)
        aoff[mt] = ldsm_off(lane, m0 + mt * 16, A_STR);
    __syncthreads();

    float acc[4][4][4] = {};
#pragma unroll 1
    for (int c = 0; c < 8; c++) {
        if (c < 7) {
            const float* src = W + (size_t)((c + 1) * 16 + wrow) * 128 + wcol;
            uint32_t dst = ws_u32
                         + (uint32_t)((((c + 1) & 1) * 16 + wrow) * W_STR + wcol) * 4;
            cp_async16(dst, src);
            cp_async16(dst + 16, src + 4);
        }
        CP_COMMIT();
        if (c < 7) cp_wait<1>(); else cp_wait<0>();
        __syncthreads();

        const float* wb = Wsf + (c & 1) * WBUF_WORDS;
#pragma unroll
        for (int kk = 0; kk < 2; kk++) {
            uint32_t b[4][2];
            const float* w0 = wb + (kk * 8 + t) * W_STR + n0 + g;
            const float* w1 = w0 + 4 * W_STR;
#pragma unroll
            for (int nt = 0; nt < 4; nt++) {
                b[nt][0] = f2tf32(w0[nt * 8]);
                b[nt][1] = f2tf32(w1[nt * 8]);
            }
            uint32_t a[4][4];
            int k0 = c * 16 + kk * 8;
#pragma unroll
            for (int mt = 0; mt < 4; mt++)
                ldsm_x4(a[mt], As + aoff[mt] + k0);
#pragma unroll
            for (int mt = 0; mt < 4; mt++)
#pragma unroll
                for (int nt = 0; nt < 4; nt++)
                    mma_tf32(acc[mt][nt], a[mt], b[nt]);
        }
        __syncthreads();
    }

    float bb[4][2];
#pragma unroll
    for (int nt = 0; nt < 4; nt++) {
        int d = n0 + nt * 8 + 2 * t;
        bb[nt][0] = bias[d];
        bb[nt][1] = bias[d + 1];
    }
#pragma unroll
    for (int mt = 0; mt < 4; mt++)
#pragma unroll
        for (int h = 0; h < 2; h++) {
            int r = m0 + mt * 16 + g + h * 8;
            float* op = out + ((size_t)bm * 128 + r) * 128;
#pragma unroll
            for (int nt = 0; nt < 4; nt++) {
                int d = n0 + nt * 8 + 2 * t;
                float2 v = make_float2(acc[mt][nt][2 * h]     + bb[nt][0],
                                       acc[mt][nt][2 * h + 1] + bb[nt][1]);
                *(float2*)&op[d] = v;
            }
        }
}

// ---------------------------------------------------------------------------
// Kernel 2: attention (identical to R16). One block per (window, head).
// ---------------------------------------------------------------------------
__global__ __launch_bounds__(128) void attn_mma()
{
    __shared__ uint32_t sQK[64 * 72];
    __shared__ uint32_t sV[64 * 40];

    uint32_t* sQ = sQK;
    uint32_t* sK = sQK + 2304;
    uint32_t* sP = sQK;

    int tid  = threadIdx.x;
    int lane = tid & 31, warp = tid >> 5;
    int g = lane >> 2, t = lane & 3;
    int wh   = blockIdx.x;
    int head = wh & 3;
    int widx = wh >> 2;
    int bimg = widx >> 6;
    int win  = widx & 63;
    const uint4* qp = (const uint4*)(g_qkv + (size_t)wh * 1568);
    const uint4* kp = (const uint4*)(g_qkv + (size_t)(16384 + wh) * 1568);
    const uint4* vp = (const uint4*)(g_qkv + (size_t)(2 * 16384 + wh) * 1568);
    const float* combp = g_comb + (size_t)(win * 4 + head) * 2401;

    for (int idx = tid; idx < 512; idx += 128) {
        int l = idx >> 3, c4 = (idx & 7) << 2;
        uint4 z = make_uint4(0u, 0u, 0u, 0u);
        uint4 q4 = z, k4 = z, v4 = z;
        if (l < 49) {
            int e = (l * 32 + c4) >> 2;
            q4 = qp[e]; k4 = kp[e]; v4 = vp[e];
        }
        *(uint4*)&sQ[l * 36 + c4] = q4;
        *(uint4*)&sK[l * 36 + c4] = k4;
        *(uint4*)&sV[l * 40 + c4] = v4;
    }
    __syncthreads();

    int m0 = warp * 16;
    int qoff = ldsm_off(lane, m0, 36);
    int poff = ldsm_off(lane, m0, 72);

    float acc[8][4] = {};
#pragma unroll
    for (int k0 = 0; k0 < 32; k0 += 8) {
        uint32_t a[4];
        ldsm_x4(a, sQ + qoff + k0);
#pragma unroll
        for (int nt = 0; nt < 8; nt++) {
            uint32_t b[2];
            int bb = (nt * 8 + g) * 36 + k0 + t;
            b[0] = sK[bb];
            b[1] = sK[bb + 4];
            mma_tf32(acc[nt], a, b);
        }
    }

    float inv2[2];
    {
        const float scale = 0.17677669529663687f;
        float mx2[2], sm2[2];
#pragma unroll
        for (int h = 0; h < 2; h++) {
            int i = m0 + g + h * 8;
            float c[8][2];
#pragma unroll
            for (int nt = 0; nt < 8; nt++)
#pragma unroll
                for (int e = 0; e < 2; e++) {
                    int j = nt * 8 + 2 * t + e;
                    c[nt][e] = (i < 49 && j < 49)
                             ? __ldg(combp + i * 49 + j) : -1e30f;
                }
            float mx = -1e30f;
#pragma unroll
            for (int nt = 0; nt < 8; nt++)
#pragma unroll
                for (int e = 0; e < 2; e++) {
                    float v = acc[nt][2 * h + e] * scale + c[nt][e];
                    acc[nt][2 * h + e] = v;
                    mx = fmaxf(mx, v);
                }
            mx = fmaxf(mx, __shfl_xor_sync(0xffffffffu, mx, 1));
            mx = fmaxf(mx, __shfl_xor_sync(0xffffffffu, mx, 2));
            mx2[h] = mx;
        }
#pragma unroll
        for (int h = 0; h < 2; h++) {
            float sum = 0.f;
#pragma unroll
            for (int nt = 0; nt < 8; nt++)
#pragma unroll
                for (int e = 0; e < 2; e++) {
                    float p = __expf(acc[nt][2 * h + e] - mx2[h]);
                    acc[nt][2 * h + e] = p;
                    sum += p;
                }
            sum += __shfl_xor_sync(0xffffffffu, sum, 1);
            sum += __shfl_xor_sync(0xffffffffu, sum, 2);
            sm2[h] = sum;
        }
        inv2[0] = 1.f / sm2[0];
        inv2[1] = 1.f / sm2[1];
    }

    __syncthreads();

#pragma unroll
    for (int h = 0; h < 2; h++) {
        float inv = inv2[h];
        int row = m0 + g + h * 8;
#pragma unroll
        for (int nt = 0; nt < 8; nt++) {
            uint2 v = make_uint2(f2tf32(acc[nt][2 * h]     * inv),
                                 f2tf32(acc[nt][2 * h + 1] * inv));
            *(uint2*)&sP[row * 72 + nt * 8 + 2 * t] = v;
        }
    }
    __syncwarp();

    {
        float oac[4][4] = {};
#pragma unroll
        for (int k0 = 0; k0 < 64; k0 += 8) {
            uint32_t a[4];
            ldsm_x4(a, sP + poff + k0);
#pragma unroll
            for (int nt = 0; nt < 4; nt++) {
                uint32_t b[2];
                int bb = (k0 + t) * 40 + nt * 8 + g;
                b[0] = sV[bb];
                b[1] = sV[bb + 4 * 40];
                mma_tf32(oac[nt], a, b);
            }
        }
        int ybase = (win >> 3) * 7;
        int xbase = (win & 7) * 7;
#pragma unroll
        for (int h = 0; h < 2; h++) {
            int i = m0 + g + h * 8;
            if (i < 49) {
                int wy = i / 7, wx = i - wy * 7;
                float* op = g_att + (((size_t)(bimg * 56 + ybase + wy)) * 56 + (xbase + wx)) * 128
                          + head * 32;
#pragma unroll
                for (int nt = 0; nt < 4; nt++) {
                    uint2 v = make_uint2(f2tf32(oac[nt][2 * h]),
                                         f2tf32(oac[nt][2 * h + 1]));
                    *(uint2*)&op[nt * 8 + 2 * t] = v;
                }
            }
        }
    }
}

// ---------------------------------------------------------------------------
extern "C" void kernel_launch(void* const* d_in, const int* in_sizes, int n_in,
                              void* d_out, int out_size)
{
    const float* x      = nullptr;
    const int*   relidx = nullptr;
    const float* mask   = nullptr;
    const float* qkv_w  = nullptr;
    const float* qkv_b  = nullptr;
    const float* relt   = nullptr;
    const float* proj_w = nullptr;
    const float* proj_b = nullptr;

    for (int i = 0; i < n_in; i++) {
        switch (in_sizes[i]) {
            case 25690112: x      = (const float*)d_in[i]; break;
            case 2401:     relidx = (const int*)  d_in[i]; break;
            case 153664:   mask   = (const float*)d_in[i]; break;
            case 49152:    qkv_w  = (const float*)d_in[i]; break;
            case 384:      qkv_b  = (const float*)d_in[i]; break;
            case 676:      relt   = (const float*)d_in[i]; break;
            case 16384:    proj_w = (const float*)d_in[i]; break;
            case 128:      proj_b = (const float*)d_in[i]; break;
            default: break;
        }
    }

    cudaFuncSetAttribute(qkv_gemm_mma,  cudaFuncAttributeMaxDynamicSharedMemorySize, SM_GEMM_BYTES);
    cudaFuncSetAttribute(proj_gemm_mma, cudaFuncAttributeMaxDynamicSharedMemorySize, SM_GEMM_BYTES);

    combine_bias<<<(COMB_ELEMS + 255) / 256, 256>>>(relidx, mask, relt);

    qkv_gemm_mma<<<TOKENS / 128, 256, SM_GEMM_BYTES>>>(x, qkv_w, qkv_b);

    attn_mma<<<WH_TOTAL, 128>>>();

    proj_gemm_mma<<<TOKENS / 128, 256, SM_GEMM_BYTES>>>(proj_w, proj_b, (float*)d_out);
}